// round 14
// baseline (speedup 1.0000x reference)
#include <cuda_runtime.h>
#include <cuda_fp16.h>
#include <cstdint>

#define NB    65536
#define DIM   256
#define HID   64
#define ACT   18
#define NEXP  8
#define ROWS  128
#define NTHR  128
#define HPAD  72        // halves per row stride (144B) -> conflict-free ldmatrix
#define TILES_PER_EXP 128

// smem: W double buffer + bias
#define SWSZ   18432
#define SBIAS  (2 * SWSZ)
#define SMEM_TOTAL (SBIAS + 1408)

// ---------------- scratch ----------------
#define HB 64
__device__ int g_part[HB * NEXP];
__device__ int g_offsets[NEXP + 1];
__device__ int g_perm[NB];
__device__ int g_bar = 0;      // monotone epoch barrier (never reset; replay-safe)
// per expert 9 slots (W1 c0..c3, W2..W5, W6) of 8192 halves:
// hi plane [0,4096), lo plane [4096,8192); layout [n][64 k]
__device__ __align__(16) __half g_w[NEXP * 9 * 8192];

#define WCB (NEXP * 9)   // 72 weight-tile conversion blocks

// ---------------- single prologue: hist -> grid barrier -> scatter || wconv ----------------
__global__ void k_pre(const int4* __restrict__ rm,
                      const float* __restrict__ W1, const float* __restrict__ W2,
                      const float* __restrict__ W3, const float* __restrict__ W4,
                      const float* __restrict__ W5, const float* __restrict__ W6) {
    __shared__ float sm[64 * 65];
    __shared__ int s_tgt;
    int b = blockIdx.x, t = threadIdx.x;
    if (b < HB) {
        // ---- phase 1: histogram ----
        int* s_base = (int*)sm;
        int* s_cnt  = (int*)sm + NEXP;
        if (t < NEXP) s_cnt[t] = 0;
        __syncthreads();
        int4 v = rm[b * 256 + t];
        int vv[4] = { v.x, v.y, v.z, v.w };
        #pragma unroll
        for (int r = 0; r < 4; r++) {
            unsigned m = __match_any_sync(0xffffffffu, vv[r]);
            if ((t & 31) == __ffs(m) - 1) atomicAdd(&s_cnt[vv[r]], __popc(m));
        }
        __syncthreads();
        if (t < NEXP) g_part[b * NEXP + t] = s_cnt[t];
        // ---- grid barrier over the 64 hist blocks (all co-resident) ----
        __threadfence();                       // release g_part
        if (t == 0) {
            int ticket = atomicAdd(&g_bar, 1);
            s_tgt = (ticket / HB + 1) * HB;
        }
        __syncthreads();
        if (t == 0) {
            volatile int* vb = &g_bar;
            while (*vb < s_tgt) { }
        }
        __syncthreads();
        __threadfence();                       // acquire g_part
        // ---- phase 2: prefix + scatter ----
        if (t < NEXP) {
            int col = 0, pre = 0;
            #pragma unroll
            for (int bb = 0; bb < HB; bb++) {
                int vv2 = g_part[bb * NEXP + t];
                col += vv2;
                if (bb < b) pre += vv2;
            }
            int offs = 0;
            #pragma unroll
            for (int u = 0; u < NEXP; u++) {
                int cv = __shfl_sync(0x000000ffu, col, u);
                if (u < t) offs += cv;
            }
            s_base[t] = offs + pre;
            s_cnt[t] = 0;
            if (b == 0) {
                g_offsets[t] = offs;
                if (t == NEXP - 1) g_offsets[NEXP] = offs + col;
            }
        }
        __syncthreads();
        unsigned lt = (1u << (t & 31)) - 1u;
        int i4 = (b * 256 + t) * 4;
        #pragma unroll
        for (int r = 0; r < 4; r++) {
            unsigned m = __match_any_sync(0xffffffffu, vv[r]);
            int leader = __ffs(m) - 1;
            int base = 0;
            if ((t & 31) == leader) base = atomicAdd(&s_cnt[vv[r]], __popc(m));
            base = __shfl_sync(0xffffffffu, base, leader);
            g_perm[s_base[vv[r]] + base + __popc(m & lt)] = i4 + r;
        }
        return;
    }
    // ---- weight tile conversion (independent of barrier) ----
    int s = (b - HB) % 9, e = (b - HB) / 9;
    int base = (e * 9 + s) * 8192;
    if (s < 8) {
        const float* src;
        if (s < 4)       src = W1 + (size_t)e * 16384 + s * 4096;
        else if (s == 4) src = W2 + (size_t)e * 4096;
        else if (s == 5) src = W3 + (size_t)e * 4096;
        else if (s == 6) src = W4 + (size_t)e * 4096;
        else             src = W5 + (size_t)e * 4096;
        #pragma unroll
        for (int j = 0; j < 4; j++) {
            int f = t + j * 256;
            int row = f >> 4, c4 = (f & 15) * 4;
            float4 v = *(const float4*)(src + row * 64 + c4);
            float* d = sm + row * 65 + c4;
            d[0] = v.x; d[1] = v.y; d[2] = v.z; d[3] = v.w;
        }
        __syncthreads();
        int n = t >> 2, kb = (t & 3) * 16;
        __align__(16) __half hb[16], lb[16];
        #pragma unroll
        for (int kk = 0; kk < 16; kk++) {
            float w = sm[(kb + kk) * 65 + n];
            __half h = __float2half_rn(w);
            hb[kk] = h;
            lb[kk] = __float2half_rn(w - __half2float(h));
        }
        uint4* dh = (uint4*)&g_w[base + n * 64 + kb];
        dh[0] = *(uint4*)hb;  dh[1] = *(uint4*)(hb + 8);
        uint4* dl = (uint4*)&g_w[base + 4096 + n * 64 + kb];
        dl[0] = *(uint4*)lb;  dl[1] = *(uint4*)(lb + 8);
    } else {
        const float* src6 = W6 + (size_t)e * 64 * ACT;
        for (int i = t; i < 64 * ACT; i += 256)
            sm[(i / ACT) * 65 + (i % ACT)] = src6[i];
        __syncthreads();
        int n = t >> 3, kb = (t & 7) * 8;
        __align__(16) __half hb[8], lb[8];
        #pragma unroll
        for (int kk = 0; kk < 8; kk++) {
            float w = (n < ACT) ? sm[(kb + kk) * 65 + n] : 0.f;
            __half h = __float2half_rn(w);
            hb[kk] = h;
            lb[kk] = __float2half_rn(w - __half2float(h));
        }
        *(uint4*)&g_w[base + n * 64 + kb] = *(uint4*)hb;
        *(uint4*)&g_w[base + 4096 + n * 64 + kb] = *(uint4*)lb;
    }
}

// ---------------- helpers ----------------
__device__ __forceinline__ uint32_t smem_u32(const void* p) {
    uint32_t a;
    asm("{ .reg .u64 t; cvta.to.shared.u64 t, %1; cvt.u32.u64 %0, t; }" : "=r"(a) : "l"(p));
    return a;
}
// pack: {lo16 = f16(a), hi16 = f16(b)}
__device__ __forceinline__ uint32_t pk2(float a, float b) {
    uint32_t r;
    asm("cvt.rn.f16x2.f32 %0, %1, %2;" : "=r"(r) : "f"(b), "f"(a));
    return r;
}
#define CP16(dst, src) \
    asm volatile("cp.async.ca.shared.global [%0], [%1], 16;" :: "r"(dst), "l"(src))
#define CP_COMMIT() asm volatile("cp.async.commit_group;" ::: "memory")
#define CP_WAIT0()  asm volatile("cp.async.wait_group 0;" ::: "memory")

#define LDSM4(d, addr) \
    asm volatile("ldmatrix.sync.aligned.m8n8.x4.shared.b16 {%0,%1,%2,%3}, [%4];" \
        : "=r"((d)[0]), "=r"((d)[1]), "=r"((d)[2]), "=r"((d)[3]) : "r"(addr))

// non-volatile: ptxas may interleave/software-pipeline the MMA stream
#define MMA(c, a, b0, b1) \
    asm("mma.sync.aligned.m16n8k16.row.col.f32.f16.f16.f32 " \
        "{%0,%1,%2,%3},{%4,%5,%6,%7},{%8,%9},{%0,%1,%2,%3};" \
        : "+f"((c)[0]), "+f"((c)[1]), "+f"((c)[2]), "+f"((c)[3]) \
        : "r"((a)[0]), "r"((a)[1]), "r"((a)[2]), "r"((a)[3]), "r"(b0), "r"(b1))

__device__ __forceinline__ void stageW(uint32_t swb, const __half* gw,
                                       int tid, int nW) {
    const char* src = (const char*)gw;
    int total = nW * 8;
    #pragma unroll 4
    for (int i = tid; i < total; i += NTHR) {
        int n = i >> 3, j = i & 7;
        uint32_t d = n * (HPAD * 2) + j * 16;
        int s = (n * 64 + j * 8) * 2;
        CP16(swb + d, src + s);
        CP16(swb + 9216 + d, src + 8192 + s);
    }
}

// 8 MMAs interleaved over 4 independent accumulator chains
#define MMA8I(aA, aB, fA, fB, bh, bl) do {               \
    MMA((aA)[0], fA, (bh)[0], (bh)[1]);                  \
    MMA((aA)[1], fA, (bh)[2], (bh)[3]);                  \
    MMA((aB)[0], fB, (bh)[0], (bh)[1]);                  \
    MMA((aB)[1], fB, (bh)[2], (bh)[3]);                  \
    MMA((aA)[0], fA, (bl)[0], (bl)[1]);                  \
    MMA((aA)[1], fA, (bl)[2], (bl)[3]);                  \
    MMA((aB)[0], fB, (bl)[0], (bl)[1]);                  \
    MMA((aB)[1], fB, (bl)[2], (bl)[3]);                  \
} while (0)

// ---------------- fused MoE (32 rows/warp, fp16 2-term) ----------------
__global__ void __launch_bounds__(NTHR, 4) k_moe(
    const float* __restrict__ X,
    const float* __restrict__ b1, const float* __restrict__ b2,
    const float* __restrict__ b3, const float* __restrict__ b4,
    const float* __restrict__ b5, const float* __restrict__ b6,
    float* __restrict__ out)
{
    extern __shared__ char smem[];
    const int tid = threadIdx.x, wid = tid >> 5, lane = tid & 31;
    const int e = blockIdx.y, tile = blockIdx.x;
    const int off = g_offsets[e];
    const int cnt = g_offsets[e + 1] - off;
    if (tile * ROWS >= cnt) return;
    const int nrows = min(ROWS, cnt - tile * ROWS);

    const uint32_t sb = smem_u32(smem);
    const uint32_t wbuf[2] = { sb, sb + SWSZ };
    float* sB = (float*)(smem + SBIAS);

    const __half* gwE = g_w + (size_t)e * 9 * 8192;

    stageW(wbuf[0], gwE, tid, 64);
    CP_COMMIT();

    if (tid < 64) {
        sB[tid]       = b1[e * HID + tid];
        sB[64 + tid]  = b2[e * HID + tid];
        sB[128 + tid] = b3[e * HID + tid];
        sB[192 + tid] = b4[e * HID + tid];
        sB[256 + tid] = b5[e * HID + tid];
    }
    if (tid < 32) sB[320 + tid] = (tid < ACT) ? b6[e * ACT + tid] : 0.f;

    const uint32_t bRowL = (uint32_t)((lane & 7) + ((lane >> 4) & 1) * 8);
    const uint32_t bKof  = ((lane >> 3) & 1) * 8;

    const int erow = wid * 32 + (lane >> 2);
    int pr[4];
    const float* xr[4];
    #pragma unroll
    for (int q = 0; q < 4; q++) {
        int rr = erow + q * 8;
        pr[q] = (rr < nrows) ? g_perm[off + tile * ROWS + rr] : -1;
        xr[q] = X + (size_t)((pr[q] >= 0) ? pr[q] : g_perm[off]) * DIM;
    }
    const int cofL = (lane & 3) * 2;
    const int cofH = 8 + cofL;

    float accA[8][4], accB[8][4];
    #pragma unroll
    for (int i = 0; i < 8; i++)
        #pragma unroll
        for (int j = 0; j < 4; j++) { accA[i][j] = 0.f; accB[i][j] = 0.f; }

    float2 cur[8];
    #pragma unroll
    for (int q = 0; q < 2; q++) {
        cur[4 * q + 0] = *(const float2*)(xr[2 * q + 0] + cofL);
        cur[4 * q + 1] = *(const float2*)(xr[2 * q + 1] + cofL);
        cur[4 * q + 2] = *(const float2*)(xr[2 * q + 0] + cofH);
        cur[4 * q + 3] = *(const float2*)(xr[2 * q + 1] + cofH);
    }

    // ============ layer 1: 4 chunks of K=64 ============
    for (int c = 0; c < 4; c++) {
        CP_WAIT0();
        __syncthreads();
        stageW(wbuf[(c + 1) & 1], gwE + (c + 1) * 8192, tid, 64);
        CP_COMMIT();
        const uint32_t wb_ = wbuf[c & 1];
        #pragma unroll
        for (int ks = 0; ks < 4; ks++) {
            uint32_t fA[4], fB[4];
            #pragma unroll
            for (int q = 0; q < 4; q++) {
                fA[q] = pk2(cur[q].x, cur[q].y);
                fB[q] = pk2(cur[4 + q].x, cur[4 + q].y);
            }
            if (!(c == 3 && ks == 3)) {
                int kb = c * 64 + (ks + 1) * 16;
                if (ks == 3) kb = (c + 1) * 64;
                #pragma unroll
                for (int q = 0; q < 2; q++) {
                    cur[4 * q + 0] = *(const float2*)(xr[2 * q + 0] + kb + cofL);
                    cur[4 * q + 1] = *(const float2*)(xr[2 * q + 1] + kb + cofL);
                    cur[4 * q + 2] = *(const float2*)(xr[2 * q + 0] + kb + cofH);
                    cur[4 * q + 3] = *(const float2*)(xr[2 * q + 1] + kb + cofH);
                }
            }
            uint32_t k0 = ks * 16;
            #pragma unroll
            for (int p = 0; p < 4; p++) {
                uint32_t boff = ((p * 16 + bRowL) * HPAD + k0 + bKof) * 2;
                uint32_t bh[4], bl[4];
                LDSM4(bh, wb_ + boff);
                LDSM4(bl, wb_ + 9216 + boff);
                MMA8I((accA + 2 * p), (accB + 2 * p), fA, fB, bh, bl);
            }
        }
    }

    // ============ layers 2..5 (stages 4..7) ============
    for (int s = 4; s < 8; s++) {
        CP_WAIT0();
        __syncthreads();
        stageW(wbuf[(s + 1) & 1], gwE + (s + 1) * 8192, tid, (s == 7) ? 32 : 64);
        CP_COMMIT();
        const float* bb = sB + (s - 4) * 64;
        uint32_t fA[4][4], fB[4][4];
        #pragma unroll
        for (int kt = 0; kt < 4; kt++) {
            #pragma unroll
            for (int h = 0; h < 2; h++) {
                int nt = 2 * kt + h;
                float b0v = bb[nt * 8 + cofL], b1v = bb[nt * 8 + cofL + 1];
                float v0 = fmaxf(accA[nt][0] + b0v, 0.f);
                float v1 = fmaxf(accA[nt][1] + b1v, 0.f);
                float v2 = fmaxf(accA[nt][2] + b0v, 0.f);
                float v3 = fmaxf(accA[nt][3] + b1v, 0.f);
                fA[kt][2 * h]     = pk2(v0, v1);
                fA[kt][2 * h + 1] = pk2(v2, v3);
                float w0 = fmaxf(accB[nt][0] + b0v, 0.f);
                float w1 = fmaxf(accB[nt][1] + b1v, 0.f);
                float w2 = fmaxf(accB[nt][2] + b0v, 0.f);
                float w3 = fmaxf(accB[nt][3] + b1v, 0.f);
                fB[kt][2 * h]     = pk2(w0, w1);
                fB[kt][2 * h + 1] = pk2(w2, w3);
            }
        }
        #pragma unroll
        for (int i = 0; i < 8; i++)
            #pragma unroll
            for (int j = 0; j < 4; j++) { accA[i][j] = 0.f; accB[i][j] = 0.f; }
        #pragma unroll
        for (int ks = 0; ks < 4; ks++) {
            uint32_t k0 = ks * 16;
            #pragma unroll
            for (int p = 0; p < 4; p++) {
                uint32_t boff = ((p * 16 + bRowL) * HPAD + k0 + bKof) * 2;
                uint32_t bh[4], bl[4];
                LDSM4(bh, wbuf[s & 1] + boff);
                LDSM4(bl, wbuf[s & 1] + 9216 + boff);
                MMA8I((accA + 2 * p), (accB + 2 * p), fA[ks], fB[ks], bh, bl);
            }
        }
    }

    // ============ layer 6 (stage 8) ============
    CP_WAIT0();
    __syncthreads();
    {
        const float* bb = sB + 256;
        uint32_t fA[4][4], fB[4][4];
        #pragma unroll
        for (int kt = 0; kt < 4; kt++) {
            #pragma unroll
            for (int h = 0; h < 2; h++) {
                int nt = 2 * kt + h;
                float b0v = bb[nt * 8 + cofL], b1v = bb[nt * 8 + cofL + 1];
                float v0 = fmaxf(accA[nt][0] + b0v, 0.f);
                float v1 = fmaxf(accA[nt][1] + b1v, 0.f);
                float v2 = fmaxf(accA[nt][2] + b0v, 0.f);
                float v3 = fmaxf(accA[nt][3] + b1v, 0.f);
                fA[kt][2 * h]     = pk2(v0, v1);
                fA[kt][2 * h + 1] = pk2(v2, v3);
                float w0 = fmaxf(accB[nt][0] + b0v, 0.f);
                float w1 = fmaxf(accB[nt][1] + b1v, 0.f);
                float w2 = fmaxf(accB[nt][2] + b0v, 0.f);
                float w3 = fmaxf(accB[nt][3] + b1v, 0.f);
                fB[kt][2 * h]     = pk2(w0, w1);
                fB[kt][2 * h + 1] = pk2(w2, w3);
            }
        }
        float acc6A[4][4], acc6B[4][4];
        #pragma unroll
        for (int i = 0; i < 4; i++)
            #pragma unroll
            for (int j = 0; j < 4; j++) { acc6A[i][j] = 0.f; acc6B[i][j] = 0.f; }

        const uint32_t wb_ = wbuf[0];
        #pragma unroll
        for (int ks = 0; ks < 4; ks++) {
            uint32_t k0 = ks * 16;
            #pragma unroll
            for (int p = 0; p < 2; p++) {
                uint32_t boff = ((p * 16 + bRowL) * HPAD + k0 + bKof) * 2;
                uint32_t bh[4], bl[4];
                LDSM4(bh, wb_ + boff);
                LDSM4(bl, wb_ + 9216 + boff);
                MMA8I((acc6A + 2 * p), (acc6B + 2 * p), fA[ks], fB[ks], bh, bl);
            }
        }

        const float* b6b = sB + 320;
        #pragma unroll
        for (int nt = 0; nt < 3; nt++) {
            int c0 = nt * 8 + cofL;
            if (c0 + 1 < ACT) {
                float b0v = b6b[c0], b1v = b6b[c0 + 1];
                if (pr[0] >= 0) {
                    out[(size_t)pr[0] * ACT + c0]     = acc6A[nt][0] + b0v;
                    out[(size_t)pr[0] * ACT + c0 + 1] = acc6A[nt][1] + b1v;
                }
                if (pr[1] >= 0) {
                    out[(size_t)pr[1] * ACT + c0]     = acc6A[nt][2] + b0v;
                    out[(size_t)pr[1] * ACT + c0 + 1] = acc6A[nt][3] + b1v;
                }
                if (pr[2] >= 0) {
                    out[(size_t)pr[2] * ACT + c0]     = acc6B[nt][0] + b0v;
                    out[(size_t)pr[2] * ACT + c0 + 1] = acc6B[nt][1] + b1v;
                }
                if (pr[3] >= 0) {
                    out[(size_t)pr[3] * ACT + c0]     = acc6B[nt][2] + b0v;
                    out[(size_t)pr[3] * ACT + c0 + 1] = acc6B[nt][3] + b1v;
                }
            }
        }
    }
}

extern "C" void kernel_launch(void* const* d_in, const int* in_sizes, int n_in,
                              void* d_out, int out_size) {
    const float* X  = (const float*)d_in[0];
    const int*   rm = (const int*)d_in[1];
    const float* W1 = (const float*)d_in[2];  const float* b1 = (const float*)d_in[3];
    const float* W2 = (const float*)d_in[4];  const float* b2 = (const float*)d_in[5];
    const float* W3 = (const float*)d_in[6];  const float* b3 = (const float*)d_in[7];
    const float* W4 = (const float*)d_in[8];  const float* b4 = (const float*)d_in[9];
    const float* W5 = (const float*)d_in[10]; const float* b5 = (const float*)d_in[11];
    const float* W6 = (const float*)d_in[12]; const float* b6 = (const float*)d_in[13];
    float* out = (float*)d_out;

    cudaFuncSetAttribute(k_moe, cudaFuncAttributeMaxDynamicSharedMemorySize, SMEM_TOTAL);

    k_pre<<<HB + WCB, 256>>>((const int4*)rm, W1, W2, W3, W4, W5, W6);

    dim3 grid(TILES_PER_EXP, NEXP);
    k_moe<<<grid, NTHR, SMEM_TOTAL>>>(X, b1, b2, b3, b4, b5, b6, out);
}

// round 15
// speedup vs baseline: 1.0577x; 1.0577x over previous
#include <cuda_runtime.h>
#include <cuda_fp16.h>
#include <cstdint>

#define NB    65536
#define DIM   256
#define HID   64
#define ACT   18
#define NEXP  8
#define ROWS  256
#define NTHR  256
#define HPAD  72        // halves per row stride (144B) -> conflict-free ldmatrix
#define TILES_PER_EXP 64   // 16384-row capacity per expert

// smem: W double buffer + bias
#define SWSZ   18432
#define SBIAS  (2 * SWSZ)
#define SMEM_TOTAL (SBIAS + 1408)

// ---------------- scratch ----------------
#define HB 64
__device__ int g_part[HB * NEXP];
__device__ int g_offsets[NEXP + 1];
__device__ int g_perm[NB];
// per expert 9 slots (W1 c0..c3, W2..W5, W6) of 8192 halves:
// hi plane [0,4096), lo plane [4096,8192); layout [n][64 k]
__device__ __align__(16) __half g_w[NEXP * 9 * 8192];

#define WCB (NEXP * 9)   // 72 weight-tile conversion blocks

// ---------------- launch 1: histogram only ----------------
__global__ void k_hist(const int4* __restrict__ rm) {
    __shared__ int s_cnt[NEXP];
    int b = blockIdx.x, t = threadIdx.x;
    if (t < NEXP) s_cnt[t] = 0;
    __syncthreads();
    int4 v = rm[b * 256 + t];
    int vv[4] = { v.x, v.y, v.z, v.w };
    #pragma unroll
    for (int r = 0; r < 4; r++) {
        unsigned m = __match_any_sync(0xffffffffu, vv[r]);
        if ((t & 31) == __ffs(m) - 1) atomicAdd(&s_cnt[vv[r]], __popc(m));
    }
    __syncthreads();
    if (t < NEXP) g_part[b * NEXP + t] = s_cnt[t];
}

// ---------------- launch 2: scatter (blocks 0..63) || wconv (blocks 64..135) ----------------
__global__ void k_pre2(const int4* __restrict__ rm,
                       const float* __restrict__ W1, const float* __restrict__ W2,
                       const float* __restrict__ W3, const float* __restrict__ W4,
                       const float* __restrict__ W5, const float* __restrict__ W6) {
    __shared__ float sm[64 * 65];
    int b = blockIdx.x, t = threadIdx.x;
    if (b < HB) {
        int* s_base = (int*)sm;
        int* s_cnt  = (int*)sm + NEXP;
        if (t < NEXP) {
            int col = 0, pre = 0;
            #pragma unroll
            for (int bb = 0; bb < HB; bb++) {
                int v = g_part[bb * NEXP + t];
                col += v;
                if (bb < b) pre += v;
            }
            int offs = 0;
            #pragma unroll
            for (int u = 0; u < NEXP; u++) {
                int cv = __shfl_sync(0x000000ffu, col, u);
                if (u < t) offs += cv;
            }
            s_base[t] = offs + pre;
            s_cnt[t] = 0;
            if (b == 0) {
                g_offsets[t] = offs;
                if (t == NEXP - 1) g_offsets[NEXP] = offs + col;
            }
        }
        __syncthreads();
        int4 v = rm[b * 256 + t];
        int vv[4] = { v.x, v.y, v.z, v.w };
        unsigned lt = (1u << (t & 31)) - 1u;
        int i4 = (b * 256 + t) * 4;
        #pragma unroll
        for (int r = 0; r < 4; r++) {
            unsigned m = __match_any_sync(0xffffffffu, vv[r]);
            int leader = __ffs(m) - 1;
            int base = 0;
            if ((t & 31) == leader) base = atomicAdd(&s_cnt[vv[r]], __popc(m));
            base = __shfl_sync(0xffffffffu, base, leader);
            g_perm[s_base[vv[r]] + base + __popc(m & lt)] = i4 + r;
        }
        return;
    }
    // ---- weight tile conversion ----
    int s = (b - HB) % 9, e = (b - HB) / 9;
    int base = (e * 9 + s) * 8192;
    if (s < 8) {
        const float* src;
        if (s < 4)       src = W1 + (size_t)e * 16384 + s * 4096;
        else if (s == 4) src = W2 + (size_t)e * 4096;
        else if (s == 5) src = W3 + (size_t)e * 4096;
        else if (s == 6) src = W4 + (size_t)e * 4096;
        else             src = W5 + (size_t)e * 4096;
        #pragma unroll
        for (int j = 0; j < 4; j++) {
            int f = t + j * 256;
            int row = f >> 4, c4 = (f & 15) * 4;
            float4 v = *(const float4*)(src + row * 64 + c4);
            float* d = sm + row * 65 + c4;
            d[0] = v.x; d[1] = v.y; d[2] = v.z; d[3] = v.w;
        }
        __syncthreads();
        int n = t >> 2, kb = (t & 3) * 16;
        __align__(16) __half hb[16], lb[16];
        #pragma unroll
        for (int kk = 0; kk < 16; kk++) {
            float w = sm[(kb + kk) * 65 + n];
            __half h = __float2half_rn(w);
            hb[kk] = h;
            lb[kk] = __float2half_rn(w - __half2float(h));
        }
        uint4* dh = (uint4*)&g_w[base + n * 64 + kb];
        dh[0] = *(uint4*)hb;  dh[1] = *(uint4*)(hb + 8);
        uint4* dl = (uint4*)&g_w[base + 4096 + n * 64 + kb];
        dl[0] = *(uint4*)lb;  dl[1] = *(uint4*)(lb + 8);
    } else {
        const float* src6 = W6 + (size_t)e * 64 * ACT;
        for (int i = t; i < 64 * ACT; i += 256)
            sm[(i / ACT) * 65 + (i % ACT)] = src6[i];
        __syncthreads();
        int n = t >> 3, kb = (t & 7) * 8;
        __align__(16) __half hb[8], lb[8];
        #pragma unroll
        for (int kk = 0; kk < 8; kk++) {
            float w = (n < ACT) ? sm[(kb + kk) * 65 + n] : 0.f;
            __half h = __float2half_rn(w);
            hb[kk] = h;
            lb[kk] = __float2half_rn(w - __half2float(h));
        }
        *(uint4*)&g_w[base + n * 64 + kb] = *(uint4*)hb;
        *(uint4*)&g_w[base + 4096 + n * 64 + kb] = *(uint4*)lb;
    }
}

// ---------------- helpers ----------------
__device__ __forceinline__ uint32_t smem_u32(const void* p) {
    uint32_t a;
    asm("{ .reg .u64 t; cvta.to.shared.u64 t, %1; cvt.u32.u64 %0, t; }" : "=r"(a) : "l"(p));
    return a;
}
__device__ __forceinline__ uint32_t pk2(float a, float b) {
    uint32_t r;
    asm("cvt.rn.f16x2.f32 %0, %1, %2;" : "=r"(r) : "f"(b), "f"(a));
    return r;
}
#define CP16(dst, src) \
    asm volatile("cp.async.ca.shared.global [%0], [%1], 16;" :: "r"(dst), "l"(src))
#define CP_COMMIT() asm volatile("cp.async.commit_group;" ::: "memory")
#define CP_WAIT0()  asm volatile("cp.async.wait_group 0;" ::: "memory")

#define LDSM4(d, addr) \
    asm volatile("ldmatrix.sync.aligned.m8n8.x4.shared.b16 {%0,%1,%2,%3}, [%4];" \
        : "=r"((d)[0]), "=r"((d)[1]), "=r"((d)[2]), "=r"((d)[3]) : "r"(addr))

// non-volatile: ptxas may interleave/software-pipeline the MMA stream
#define MMA(c, a, b0, b1) \
    asm("mma.sync.aligned.m16n8k16.row.col.f32.f16.f16.f32 " \
        "{%0,%1,%2,%3},{%4,%5,%6,%7},{%8,%9},{%0,%1,%2,%3};" \
        : "+f"((c)[0]), "+f"((c)[1]), "+f"((c)[2]), "+f"((c)[3]) \
        : "r"((a)[0]), "r"((a)[1]), "r"((a)[2]), "r"((a)[3]), "r"(b0), "r"(b1))

__device__ __forceinline__ void stageW(uint32_t swb, const __half* gw,
                                       int tid, int nW) {
    const char* src = (const char*)gw;
    int total = nW * 8;
    #pragma unroll 2
    for (int i = tid; i < total; i += NTHR) {
        int n = i >> 3, j = i & 7;
        uint32_t d = n * (HPAD * 2) + j * 16;
        int s = (n * 64 + j * 8) * 2;
        CP16(swb + d, src + s);
        CP16(swb + 9216 + d, src + 8192 + s);
    }
}

// 8 MMAs interleaved over 4 independent accumulator chains
#define MMA8I(aA, aB, fA, fB, bh, bl) do {               \
    MMA((aA)[0], fA, (bh)[0], (bh)[1]);                  \
    MMA((aA)[1], fA, (bh)[2], (bh)[3]);                  \
    MMA((aB)[0], fB, (bh)[0], (bh)[1]);                  \
    MMA((aB)[1], fB, (bh)[2], (bh)[3]);                  \
    MMA((aA)[0], fA, (bl)[0], (bl)[1]);                  \
    MMA((aA)[1], fA, (bl)[2], (bl)[3]);                  \
    MMA((aB)[0], fB, (bl)[0], (bl)[1]);                  \
    MMA((aB)[1], fB, (bl)[2], (bl)[3]);                  \
} while (0)

// ---------------- fused MoE (8 warps x 32 rows, fp16 2-term) ----------------
__global__ void __launch_bounds__(NTHR, 2) k_moe(
    const float* __restrict__ X,
    const float* __restrict__ b1, const float* __restrict__ b2,
    const float* __restrict__ b3, const float* __restrict__ b4,
    const float* __restrict__ b5, const float* __restrict__ b6,
    float* __restrict__ out)
{
    extern __shared__ char smem[];
    const int tid = threadIdx.x, wid = tid >> 5, lane = tid & 31;
    const int e = blockIdx.y, tile = blockIdx.x;
    const int off = g_offsets[e];
    const int cnt = g_offsets[e + 1] - off;
    if (tile * ROWS >= cnt) return;
    const int nrows = min(ROWS, cnt - tile * ROWS);

    const uint32_t sb = smem_u32(smem);
    const uint32_t wbuf[2] = { sb, sb + SWSZ };
    float* sB = (float*)(smem + SBIAS);

    const __half* gwE = g_w + (size_t)e * 9 * 8192;

    stageW(wbuf[0], gwE, tid, 64);
    CP_COMMIT();

    if (tid < 64) {
        sB[tid]       = b1[e * HID + tid];
        sB[64 + tid]  = b2[e * HID + tid];
        sB[128 + tid] = b3[e * HID + tid];
        sB[192 + tid] = b4[e * HID + tid];
        sB[256 + tid] = b5[e * HID + tid];
    }
    if (tid < 32) sB[320 + tid] = (tid < ACT) ? b6[e * ACT + tid] : 0.f;

    const uint32_t bRowL = (uint32_t)((lane & 7) + ((lane >> 4) & 1) * 8);
    const uint32_t bKof  = ((lane >> 3) & 1) * 8;

    const int erow = wid * 32 + (lane >> 2);
    int pr[4];
    const float* xr[4];
    #pragma unroll
    for (int q = 0; q < 4; q++) {
        int rr = erow + q * 8;
        pr[q] = (rr < nrows) ? g_perm[off + tile * ROWS + rr] : -1;
        xr[q] = X + (size_t)((pr[q] >= 0) ? pr[q] : g_perm[off]) * DIM;
    }
    const int cofL = (lane & 3) * 2;
    const int cofH = 8 + cofL;

    float accA[8][4], accB[8][4];
    #pragma unroll
    for (int i = 0; i < 8; i++)
        #pragma unroll
        for (int j = 0; j < 4; j++) { accA[i][j] = 0.f; accB[i][j] = 0.f; }

    float2 cur[8];
    #pragma unroll
    for (int q = 0; q < 2; q++) {
        cur[4 * q + 0] = *(const float2*)(xr[2 * q + 0] + cofL);
        cur[4 * q + 1] = *(const float2*)(xr[2 * q + 1] + cofL);
        cur[4 * q + 2] = *(const float2*)(xr[2 * q + 0] + cofH);
        cur[4 * q + 3] = *(const float2*)(xr[2 * q + 1] + cofH);
    }

    // ============ layer 1: 4 chunks of K=64 ============
    for (int c = 0; c < 4; c++) {
        CP_WAIT0();
        __syncthreads();
        stageW(wbuf[(c + 1) & 1], gwE + (c + 1) * 8192, tid, 64);
        CP_COMMIT();
        const uint32_t wb_ = wbuf[c & 1];
        #pragma unroll
        for (int ks = 0; ks < 4; ks++) {
            uint32_t fA[4], fB[4];
            #pragma unroll
            for (int q = 0; q < 4; q++) {
                fA[q] = pk2(cur[q].x, cur[q].y);
                fB[q] = pk2(cur[4 + q].x, cur[4 + q].y);
            }
            if (!(c == 3 && ks == 3)) {
                int kb = c * 64 + (ks + 1) * 16;
                if (ks == 3) kb = (c + 1) * 64;
                #pragma unroll
                for (int q = 0; q < 2; q++) {
                    cur[4 * q + 0] = *(const float2*)(xr[2 * q + 0] + kb + cofL);
                    cur[4 * q + 1] = *(const float2*)(xr[2 * q + 1] + kb + cofL);
                    cur[4 * q + 2] = *(const float2*)(xr[2 * q + 0] + kb + cofH);
                    cur[4 * q + 3] = *(const float2*)(xr[2 * q + 1] + kb + cofH);
                }
            }
            uint32_t k0 = ks * 16;
            #pragma unroll
            for (int p = 0; p < 4; p++) {
                uint32_t boff = ((p * 16 + bRowL) * HPAD + k0 + bKof) * 2;
                uint32_t bh[4], bl[4];
                LDSM4(bh, wb_ + boff);
                LDSM4(bl, wb_ + 9216 + boff);
                MMA8I((accA + 2 * p), (accB + 2 * p), fA, fB, bh, bl);
            }
        }
    }

    // ============ layers 2..5 (stages 4..7) ============
    for (int s = 4; s < 8; s++) {
        CP_WAIT0();
        __syncthreads();
        stageW(wbuf[(s + 1) & 1], gwE + (s + 1) * 8192, tid, (s == 7) ? 32 : 64);
        CP_COMMIT();
        const float* bb = sB + (s - 4) * 64;
        uint32_t fA[4][4], fB[4][4];
        #pragma unroll
        for (int kt = 0; kt < 4; kt++) {
            #pragma unroll
            for (int h = 0; h < 2; h++) {
                int nt = 2 * kt + h;
                float b0v = bb[nt * 8 + cofL], b1v = bb[nt * 8 + cofL + 1];
                float v0 = fmaxf(accA[nt][0] + b0v, 0.f);
                float v1 = fmaxf(accA[nt][1] + b1v, 0.f);
                float v2 = fmaxf(accA[nt][2] + b0v, 0.f);
                float v3 = fmaxf(accA[nt][3] + b1v, 0.f);
                fA[kt][2 * h]     = pk2(v0, v1);
                fA[kt][2 * h + 1] = pk2(v2, v3);
                float w0 = fmaxf(accB[nt][0] + b0v, 0.f);
                float w1 = fmaxf(accB[nt][1] + b1v, 0.f);
                float w2 = fmaxf(accB[nt][2] + b0v, 0.f);
                float w3 = fmaxf(accB[nt][3] + b1v, 0.f);
                fB[kt][2 * h]     = pk2(w0, w1);
                fB[kt][2 * h + 1] = pk2(w2, w3);
            }
        }
        #pragma unroll
        for (int i = 0; i < 8; i++)
            #pragma unroll
            for (int j = 0; j < 4; j++) { accA[i][j] = 0.f; accB[i][j] = 0.f; }
        #pragma unroll
        for (int ks = 0; ks < 4; ks++) {
            uint32_t k0 = ks * 16;
            #pragma unroll
            for (int p = 0; p < 4; p++) {
                uint32_t boff = ((p * 16 + bRowL) * HPAD + k0 + bKof) * 2;
                uint32_t bh[4], bl[4];
                LDSM4(bh, wbuf[s & 1] + boff);
                LDSM4(bl, wbuf[s & 1] + 9216 + boff);
                MMA8I((accA + 2 * p), (accB + 2 * p), fA[ks], fB[ks], bh, bl);
            }
        }
    }

    // ============ layer 6 (stage 8) ============
    CP_WAIT0();
    __syncthreads();
    {
        const float* bb = sB + 256;
        uint32_t fA[4][4], fB[4][4];
        #pragma unroll
        for (int kt = 0; kt < 4; kt++) {
            #pragma unroll
            for (int h = 0; h < 2; h++) {
                int nt = 2 * kt + h;
                float b0v = bb[nt * 8 + cofL], b1v = bb[nt * 8 + cofL + 1];
                float v0 = fmaxf(accA[nt][0] + b0v, 0.f);
                float v1 = fmaxf(accA[nt][1] + b1v, 0.f);
                float v2 = fmaxf(accA[nt][2] + b0v, 0.f);
                float v3 = fmaxf(accA[nt][3] + b1v, 0.f);
                fA[kt][2 * h]     = pk2(v0, v1);
                fA[kt][2 * h + 1] = pk2(v2, v3);
                float w0 = fmaxf(accB[nt][0] + b0v, 0.f);
                float w1 = fmaxf(accB[nt][1] + b1v, 0.f);
                float w2 = fmaxf(accB[nt][2] + b0v, 0.f);
                float w3 = fmaxf(accB[nt][3] + b1v, 0.f);
                fB[kt][2 * h]     = pk2(w0, w1);
                fB[kt][2 * h + 1] = pk2(w2, w3);
            }
        }
        float acc6A[4][4], acc6B[4][4];
        #pragma unroll
        for (int i = 0; i < 4; i++)
            #pragma unroll
            for (int j = 0; j < 4; j++) { acc6A[i][j] = 0.f; acc6B[i][j] = 0.f; }

        const uint32_t wb_ = wbuf[0];
        #pragma unroll
        for (int ks = 0; ks < 4; ks++) {
            uint32_t k0 = ks * 16;
            #pragma unroll
            for (int p = 0; p < 2; p++) {
                uint32_t boff = ((p * 16 + bRowL) * HPAD + k0 + bKof) * 2;
                uint32_t bh[4], bl[4];
                LDSM4(bh, wb_ + boff);
                LDSM4(bl, wb_ + 9216 + boff);
                MMA8I((acc6A + 2 * p), (acc6B + 2 * p), fA[ks], fB[ks], bh, bl);
            }
        }

        const float* b6b = sB + 320;
        #pragma unroll
        for (int nt = 0; nt < 3; nt++) {
            int c0 = nt * 8 + cofL;
            if (c0 + 1 < ACT) {
                float b0v = b6b[c0], b1v = b6b[c0 + 1];
                if (pr[0] >= 0) {
                    out[(size_t)pr[0] * ACT + c0]     = acc6A[nt][0] + b0v;
                    out[(size_t)pr[0] * ACT + c0 + 1] = acc6A[nt][1] + b1v;
                }
                if (pr[1] >= 0) {
                    out[(size_t)pr[1] * ACT + c0]     = acc6A[nt][2] + b0v;
                    out[(size_t)pr[1] * ACT + c0 + 1] = acc6A[nt][3] + b1v;
                }
                if (pr[2] >= 0) {
                    out[(size_t)pr[2] * ACT + c0]     = acc6B[nt][0] + b0v;
                    out[(size_t)pr[2] * ACT + c0 + 1] = acc6B[nt][1] + b1v;
                }
                if (pr[3] >= 0) {
                    out[(size_t)pr[3] * ACT + c0]     = acc6B[nt][2] + b0v;
                    out[(size_t)pr[3] * ACT + c0 + 1] = acc6B[nt][3] + b1v;
                }
            }
        }
    }
}

extern "C" void kernel_launch(void* const* d_in, const int* in_sizes, int n_in,
                              void* d_out, int out_size) {
    const float* X  = (const float*)d_in[0];
    const int*   rm = (const int*)d_in[1];
    const float* W1 = (const float*)d_in[2];  const float* b1 = (const float*)d_in[3];
    const float* W2 = (const float*)d_in[4];  const float* b2 = (const float*)d_in[5];
    const float* W3 = (const float*)d_in[6];  const float* b3 = (const float*)d_in[7];
    const float* W4 = (const float*)d_in[8];  const float* b4 = (const float*)d_in[9];
    const float* W5 = (const float*)d_in[10]; const float* b5 = (const float*)d_in[11];
    const float* W6 = (const float*)d_in[12]; const float* b6 = (const float*)d_in[13];
    float* out = (float*)d_out;

    cudaFuncSetAttribute(k_moe, cudaFuncAttributeMaxDynamicSharedMemorySize, SMEM_TOTAL);

    k_hist<<<HB, 256>>>((const int4*)rm);
    k_pre2<<<HB + WCB, 256>>>((const int4*)rm, W1, W2, W3, W4, W5, W6);

    dim3 grid(TILES_PER_EXP, NEXP);
    k_moe<<<grid, NTHR, SMEM_TOTAL>>>(X, b1, b2, b3, b4, b5, b6, out);
}

// round 16
// speedup vs baseline: 1.0725x; 1.0140x over previous
#include <cuda_runtime.h>
#include <cuda_fp16.h>
#include <cstdint>

#define NB    65536
#define DIM   256
#define HID   64
#define ACT   18
#define NEXP  8
#define ROWS  256
#define NTHR  256
#define HPAD  72        // halves per row stride (144B) -> conflict-free ldmatrix
#define TILES_PER_EXP 64   // 16384-row capacity per expert

// smem: W double buffer + bias
#define SWSZ   18432
#define SBIAS  (2 * SWSZ)
#define SMEM_TOTAL (SBIAS + 1408)

// ---------------- scratch ----------------
#define HB 64
__device__ int g_part[HB * NEXP];
__device__ int g_offsets[NEXP + 1];
__device__ int g_perm[NB];
// per expert 9 slots (W1 c0..c3, W2..W5, W6) of 8192 halves:
// hi plane [0,4096), lo plane [4096,8192); layout [n][64 k]
__device__ __align__(16) __half g_w[NEXP * 9 * 8192];

#define WCB (NEXP * 9)   // 72 weight-tile conversion blocks

// ---------------- launch 1: histogram only ----------------
__global__ void k_hist(const int4* __restrict__ rm) {
    __shared__ int s_cnt[NEXP];
    int b = blockIdx.x, t = threadIdx.x;
    if (t < NEXP) s_cnt[t] = 0;
    __syncthreads();
    int4 v = rm[b * 256 + t];
    int vv[4] = { v.x, v.y, v.z, v.w };
    #pragma unroll
    for (int r = 0; r < 4; r++) {
        unsigned m = __match_any_sync(0xffffffffu, vv[r]);
        if ((t & 31) == __ffs(m) - 1) atomicAdd(&s_cnt[vv[r]], __popc(m));
    }
    __syncthreads();
    if (t < NEXP) g_part[b * NEXP + t] = s_cnt[t];
}

// ---------------- launch 2 (PDL): scatter (0..63, waits) || wconv (64..135, no wait) ----------------
__global__ void k_pre2(const int4* __restrict__ rm,
                       const float* __restrict__ W1, const float* __restrict__ W2,
                       const float* __restrict__ W3, const float* __restrict__ W4,
                       const float* __restrict__ W5, const float* __restrict__ W6) {
    __shared__ float sm[64 * 65];
    int b = blockIdx.x, t = threadIdx.x;
    if (b < HB) {
#if __CUDA_ARCH__ >= 900
        cudaGridDependencySynchronize();   // wait for k_hist's g_part
#endif
        int* s_base = (int*)sm;
        int* s_cnt  = (int*)sm + NEXP;
        if (t < NEXP) {
            int col = 0, pre = 0;
            #pragma unroll
            for (int bb = 0; bb < HB; bb++) {
                int v = g_part[bb * NEXP + t];
                col += v;
                if (bb < b) pre += v;
            }
            int offs = 0;
            #pragma unroll
            for (int u = 0; u < NEXP; u++) {
                int cv = __shfl_sync(0x000000ffu, col, u);
                if (u < t) offs += cv;
            }
            s_base[t] = offs + pre;
            s_cnt[t] = 0;
            if (b == 0) {
                g_offsets[t] = offs;
                if (t == NEXP - 1) g_offsets[NEXP] = offs + col;
            }
        }
        __syncthreads();
        int4 v = rm[b * 256 + t];
        int vv[4] = { v.x, v.y, v.z, v.w };
        unsigned lt = (1u << (t & 31)) - 1u;
        int i4 = (b * 256 + t) * 4;
        #pragma unroll
        for (int r = 0; r < 4; r++) {
            unsigned m = __match_any_sync(0xffffffffu, vv[r]);
            int leader = __ffs(m) - 1;
            int base = 0;
            if ((t & 31) == leader) base = atomicAdd(&s_cnt[vv[r]], __popc(m));
            base = __shfl_sync(0xffffffffu, base, leader);
            g_perm[s_base[vv[r]] + base + __popc(m & lt)] = i4 + r;
        }
        return;
    }
    // ---- weight tile conversion (independent of k_hist; runs concurrently) ----
    int s = (b - HB) % 9, e = (b - HB) / 9;
    int base = (e * 9 + s) * 8192;
    if (s < 8) {
        const float* src;
        if (s < 4)       src = W1 + (size_t)e * 16384 + s * 4096;
        else if (s == 4) src = W2 + (size_t)e * 4096;
        else if (s == 5) src = W3 + (size_t)e * 4096;
        else if (s == 6) src = W4 + (size_t)e * 4096;
        else             src = W5 + (size_t)e * 4096;
        #pragma unroll
        for (int j = 0; j < 4; j++) {
            int f = t + j * 256;
            int row = f >> 4, c4 = (f & 15) * 4;
            float4 v = *(const float4*)(src + row * 64 + c4);
            float* d = sm + row * 65 + c4;
            d[0] = v.x; d[1] = v.y; d[2] = v.z; d[3] = v.w;
        }
        __syncthreads();
        int n = t >> 2, kb = (t & 3) * 16;
        __align__(16) __half hb[16], lb[16];
        #pragma unroll
        for (int kk = 0; kk < 16; kk++) {
            float w = sm[(kb + kk) * 65 + n];
            __half h = __float2half_rn(w);
            hb[kk] = h;
            lb[kk] = __float2half_rn(w - __half2float(h));
        }
        uint4* dh = (uint4*)&g_w[base + n * 64 + kb];
        dh[0] = *(uint4*)hb;  dh[1] = *(uint4*)(hb + 8);
        uint4* dl = (uint4*)&g_w[base + 4096 + n * 64 + kb];
        dl[0] = *(uint4*)lb;  dl[1] = *(uint4*)(lb + 8);
    } else {
        const float* src6 = W6 + (size_t)e * 64 * ACT;
        for (int i = t; i < 64 * ACT; i += 256)
            sm[(i / ACT) * 65 + (i % ACT)] = src6[i];
        __syncthreads();
        int n = t >> 3, kb = (t & 7) * 8;
        __align__(16) __half hb[8], lb[8];
        #pragma unroll
        for (int kk = 0; kk < 8; kk++) {
            float w = (n < ACT) ? sm[(kb + kk) * 65 + n] : 0.f;
            __half h = __float2half_rn(w);
            hb[kk] = h;
            lb[kk] = __float2half_rn(w - __half2float(h));
        }
        *(uint4*)&g_w[base + n * 64 + kb] = *(uint4*)hb;
        *(uint4*)&g_w[base + 4096 + n * 64 + kb] = *(uint4*)lb;
    }
}

// ---------------- helpers ----------------
__device__ __forceinline__ uint32_t smem_u32(const void* p) {
    uint32_t a;
    asm("{ .reg .u64 t; cvta.to.shared.u64 t, %1; cvt.u32.u64 %0, t; }" : "=r"(a) : "l"(p));
    return a;
}
__device__ __forceinline__ uint32_t pk2(float a, float b) {
    uint32_t r;
    asm("cvt.rn.f16x2.f32 %0, %1, %2;" : "=r"(r) : "f"(b), "f"(a));
    return r;
}
#define CP16(dst, src) \
    asm volatile("cp.async.ca.shared.global [%0], [%1], 16;" :: "r"(dst), "l"(src))
#define CP_COMMIT() asm volatile("cp.async.commit_group;" ::: "memory")
#define CP_WAIT0()  asm volatile("cp.async.wait_group 0;" ::: "memory")

#define LDSM4(d, addr) \
    asm volatile("ldmatrix.sync.aligned.m8n8.x4.shared.b16 {%0,%1,%2,%3}, [%4];" \
        : "=r"((d)[0]), "=r"((d)[1]), "=r"((d)[2]), "=r"((d)[3]) : "r"(addr))

// non-volatile: ptxas may interleave/software-pipeline the MMA stream
#define MMA(c, a, b0, b1) \
    asm("mma.sync.aligned.m16n8k16.row.col.f32.f16.f16.f32 " \
        "{%0,%1,%2,%3},{%4,%5,%6,%7},{%8,%9},{%0,%1,%2,%3};" \
        : "+f"((c)[0]), "+f"((c)[1]), "+f"((c)[2]), "+f"((c)[3]) \
        : "r"((a)[0]), "r"((a)[1]), "r"((a)[2]), "r"((a)[3]), "r"(b0), "r"(b1))

__device__ __forceinline__ void stageW(uint32_t swb, const __half* gw,
                                       int tid, int nW) {
    const char* src = (const char*)gw;
    int total = nW * 8;
    #pragma unroll 2
    for (int i = tid; i < total; i += NTHR) {
        int n = i >> 3, j = i & 7;
        uint32_t d = n * (HPAD * 2) + j * 16;
        int s = (n * 64 + j * 8) * 2;
        CP16(swb + d, src + s);
        CP16(swb + 9216 + d, src + 8192 + s);
    }
}

// 8 MMAs interleaved over 4 independent accumulator chains
#define MMA8I(aA, aB, fA, fB, bh, bl) do {               \
    MMA((aA)[0], fA, (bh)[0], (bh)[1]);                  \
    MMA((aA)[1], fA, (bh)[2], (bh)[3]);                  \
    MMA((aB)[0], fB, (bh)[0], (bh)[1]);                  \
    MMA((aB)[1], fB, (bh)[2], (bh)[3]);                  \
    MMA((aA)[0], fA, (bl)[0], (bl)[1]);                  \
    MMA((aA)[1], fA, (bl)[2], (bl)[3]);                  \
    MMA((aB)[0], fB, (bl)[0], (bl)[1]);                  \
    MMA((aB)[1], fB, (bl)[2], (bl)[3]);                  \
} while (0)

// ---------------- fused MoE (8 warps x 32 rows, fp16 2-term) ----------------
__global__ void __launch_bounds__(NTHR, 2) k_moe(
    const float* __restrict__ X,
    const float* __restrict__ b1, const float* __restrict__ b2,
    const float* __restrict__ b3, const float* __restrict__ b4,
    const float* __restrict__ b5, const float* __restrict__ b6,
    float* __restrict__ out)
{
    extern __shared__ char smem[];
    const int tid = threadIdx.x, wid = tid >> 5, lane = tid & 31;
    const int e = blockIdx.y, tile = blockIdx.x;

    const uint32_t sb = smem_u32(smem);
    const uint32_t wbuf[2] = { sb, sb + SWSZ };
    float* sB = (float*)(smem + SBIAS);

    // bias preload (pure inputs, safe before the PDL dependency sync)
    if (tid < 64) {
        sB[tid]       = b1[e * HID + tid];
        sB[64 + tid]  = b2[e * HID + tid];
        sB[128 + tid] = b3[e * HID + tid];
        sB[192 + tid] = b4[e * HID + tid];
        sB[256 + tid] = b5[e * HID + tid];
    }
    if (tid < 32) sB[320 + tid] = (tid < ACT) ? b6[e * ACT + tid] : 0.f;

#if __CUDA_ARCH__ >= 900
    cudaGridDependencySynchronize();   // wait for k_pre2 (g_offsets, g_perm, g_w)
#endif

    const int off = g_offsets[e];
    const int cnt = g_offsets[e + 1] - off;
    if (tile * ROWS >= cnt) return;
    const int nrows = min(ROWS, cnt - tile * ROWS);

    const __half* gwE = g_w + (size_t)e * 9 * 8192;

    stageW(wbuf[0], gwE, tid, 64);
    CP_COMMIT();

    const uint32_t bRowL = (uint32_t)((lane & 7) + ((lane >> 4) & 1) * 8);
    const uint32_t bKof  = ((lane >> 3) & 1) * 8;

    const int erow = wid * 32 + (lane >> 2);
    int pr[4];
    const float* xr[4];
    #pragma unroll
    for (int q = 0; q < 4; q++) {
        int rr = erow + q * 8;
        pr[q] = (rr < nrows) ? g_perm[off + tile * ROWS + rr] : -1;
        xr[q] = X + (size_t)((pr[q] >= 0) ? pr[q] : g_perm[off]) * DIM;
    }
    const int cofL = (lane & 3) * 2;
    const int cofH = 8 + cofL;

    float accA[8][4], accB[8][4];
    #pragma unroll
    for (int i = 0; i < 8; i++)
        #pragma unroll
        for (int j = 0; j < 4; j++) { accA[i][j] = 0.f; accB[i][j] = 0.f; }

    float2 cur[8];
    #pragma unroll
    for (int q = 0; q < 2; q++) {
        cur[4 * q + 0] = *(const float2*)(xr[2 * q + 0] + cofL);
        cur[4 * q + 1] = *(const float2*)(xr[2 * q + 1] + cofL);
        cur[4 * q + 2] = *(const float2*)(xr[2 * q + 0] + cofH);
        cur[4 * q + 3] = *(const float2*)(xr[2 * q + 1] + cofH);
    }

    // ============ layer 1: 4 chunks of K=64 ============
    for (int c = 0; c < 4; c++) {
        CP_WAIT0();
        __syncthreads();
        stageW(wbuf[(c + 1) & 1], gwE + (c + 1) * 8192, tid, 64);
        CP_COMMIT();
        const uint32_t wb_ = wbuf[c & 1];
        #pragma unroll
        for (int ks = 0; ks < 4; ks++) {
            uint32_t fA[4], fB[4];
            #pragma unroll
            for (int q = 0; q < 4; q++) {
                fA[q] = pk2(cur[q].x, cur[q].y);
                fB[q] = pk2(cur[4 + q].x, cur[4 + q].y);
            }
            if (!(c == 3 && ks == 3)) {
                int kb = c * 64 + (ks + 1) * 16;
                if (ks == 3) kb = (c + 1) * 64;
                #pragma unroll
                for (int q = 0; q < 2; q++) {
                    cur[4 * q + 0] = *(const float2*)(xr[2 * q + 0] + kb + cofL);
                    cur[4 * q + 1] = *(const float2*)(xr[2 * q + 1] + kb + cofL);
                    cur[4 * q + 2] = *(const float2*)(xr[2 * q + 0] + kb + cofH);
                    cur[4 * q + 3] = *(const float2*)(xr[2 * q + 1] + kb + cofH);
                }
            }
            uint32_t k0 = ks * 16;
            #pragma unroll
            for (int p = 0; p < 4; p++) {
                uint32_t boff = ((p * 16 + bRowL) * HPAD + k0 + bKof) * 2;
                uint32_t bh[4], bl[4];
                LDSM4(bh, wb_ + boff);
                LDSM4(bl, wb_ + 9216 + boff);
                MMA8I((accA + 2 * p), (accB + 2 * p), fA, fB, bh, bl);
            }
        }
    }

    // ============ layers 2..5 (stages 4..7) ============
    for (int s = 4; s < 8; s++) {
        CP_WAIT0();
        __syncthreads();
        stageW(wbuf[(s + 1) & 1], gwE + (s + 1) * 8192, tid, (s == 7) ? 32 : 64);
        CP_COMMIT();
        const float* bb = sB + (s - 4) * 64;
        uint32_t fA[4][4], fB[4][4];
        #pragma unroll
        for (int kt = 0; kt < 4; kt++) {
            #pragma unroll
            for (int h = 0; h < 2; h++) {
                int nt = 2 * kt + h;
                float b0v = bb[nt * 8 + cofL], b1v = bb[nt * 8 + cofL + 1];
                float v0 = fmaxf(accA[nt][0] + b0v, 0.f);
                float v1 = fmaxf(accA[nt][1] + b1v, 0.f);
                float v2 = fmaxf(accA[nt][2] + b0v, 0.f);
                float v3 = fmaxf(accA[nt][3] + b1v, 0.f);
                fA[kt][2 * h]     = pk2(v0, v1);
                fA[kt][2 * h + 1] = pk2(v2, v3);
                float w0 = fmaxf(accB[nt][0] + b0v, 0.f);
                float w1 = fmaxf(accB[nt][1] + b1v, 0.f);
                float w2 = fmaxf(accB[nt][2] + b0v, 0.f);
                float w3 = fmaxf(accB[nt][3] + b1v, 0.f);
                fB[kt][2 * h]     = pk2(w0, w1);
                fB[kt][2 * h + 1] = pk2(w2, w3);
            }
        }
        #pragma unroll
        for (int i = 0; i < 8; i++)
            #pragma unroll
            for (int j = 0; j < 4; j++) { accA[i][j] = 0.f; accB[i][j] = 0.f; }
        #pragma unroll
        for (int ks = 0; ks < 4; ks++) {
            uint32_t k0 = ks * 16;
            #pragma unroll
            for (int p = 0; p < 4; p++) {
                uint32_t boff = ((p * 16 + bRowL) * HPAD + k0 + bKof) * 2;
                uint32_t bh[4], bl[4];
                LDSM4(bh, wbuf[s & 1] + boff);
                LDSM4(bl, wbuf[s & 1] + 9216 + boff);
                MMA8I((accA + 2 * p), (accB + 2 * p), fA[ks], fB[ks], bh, bl);
            }
        }
    }

    // ============ layer 6 (stage 8) ============
    CP_WAIT0();
    __syncthreads();
    {
        const float* bb = sB + 256;
        uint32_t fA[4][4], fB[4][4];
        #pragma unroll
        for (int kt = 0; kt < 4; kt++) {
            #pragma unroll
            for (int h = 0; h < 2; h++) {
                int nt = 2 * kt + h;
                float b0v = bb[nt * 8 + cofL], b1v = bb[nt * 8 + cofL + 1];
                float v0 = fmaxf(accA[nt][0] + b0v, 0.f);
                float v1 = fmaxf(accA[nt][1] + b1v, 0.f);
                float v2 = fmaxf(accA[nt][2] + b0v, 0.f);
                float v3 = fmaxf(accA[nt][3] + b1v, 0.f);
                fA[kt][2 * h]     = pk2(v0, v1);
                fA[kt][2 * h + 1] = pk2(v2, v3);
                float w0 = fmaxf(accB[nt][0] + b0v, 0.f);
                float w1 = fmaxf(accB[nt][1] + b1v, 0.f);
                float w2 = fmaxf(accB[nt][2] + b0v, 0.f);
                float w3 = fmaxf(accB[nt][3] + b1v, 0.f);
                fB[kt][2 * h]     = pk2(w0, w1);
                fB[kt][2 * h + 1] = pk2(w2, w3);
            }
        }
        float acc6A[4][4], acc6B[4][4];
        #pragma unroll
        for (int i = 0; i < 4; i++)
            #pragma unroll
            for (int j = 0; j < 4; j++) { acc6A[i][j] = 0.f; acc6B[i][j] = 0.f; }

        const uint32_t wb_ = wbuf[0];
        #pragma unroll
        for (int ks = 0; ks < 4; ks++) {
            uint32_t k0 = ks * 16;
            #pragma unroll
            for (int p = 0; p < 2; p++) {
                uint32_t boff = ((p * 16 + bRowL) * HPAD + k0 + bKof) * 2;
                uint32_t bh[4], bl[4];
                LDSM4(bh, wb_ + boff);
                LDSM4(bl, wb_ + 9216 + boff);
                MMA8I((acc6A + 2 * p), (acc6B + 2 * p), fA[ks], fB[ks], bh, bl);
            }
        }

        const float* b6b = sB + 320;
        #pragma unroll
        for (int nt = 0; nt < 3; nt++) {
            int c0 = nt * 8 + cofL;
            if (c0 + 1 < ACT) {
                float b0v = b6b[c0], b1v = b6b[c0 + 1];
                if (pr[0] >= 0) {
                    out[(size_t)pr[0] * ACT + c0]     = acc6A[nt][0] + b0v;
                    out[(size_t)pr[0] * ACT + c0 + 1] = acc6A[nt][1] + b1v;
                }
                if (pr[1] >= 0) {
                    out[(size_t)pr[1] * ACT + c0]     = acc6A[nt][2] + b0v;
                    out[(size_t)pr[1] * ACT + c0 + 1] = acc6A[nt][3] + b1v;
                }
                if (pr[2] >= 0) {
                    out[(size_t)pr[2] * ACT + c0]     = acc6B[nt][0] + b0v;
                    out[(size_t)pr[2] * ACT + c0 + 1] = acc6B[nt][1] + b1v;
                }
                if (pr[3] >= 0) {
                    out[(size_t)pr[3] * ACT + c0]     = acc6B[nt][2] + b0v;
                    out[(size_t)pr[3] * ACT + c0 + 1] = acc6B[nt][3] + b1v;
                }
            }
        }
    }
}

extern "C" void kernel_launch(void* const* d_in, const int* in_sizes, int n_in,
                              void* d_out, int out_size) {
    const float* X  = (const float*)d_in[0];
    const int*   rm = (const int*)d_in[1];
    const float* W1 = (const float*)d_in[2];  const float* b1 = (const float*)d_in[3];
    const float* W2 = (const float*)d_in[4];  const float* b2 = (const float*)d_in[5];
    const float* W3 = (const float*)d_in[6];  const float* b3 = (const float*)d_in[7];
    const float* W4 = (const float*)d_in[8];  const float* b4 = (const float*)d_in[9];
    const float* W5 = (const float*)d_in[10]; const float* b5 = (const float*)d_in[11];
    const float* W6 = (const float*)d_in[12]; const float* b6 = (const float*)d_in[13];
    float* out = (float*)d_out;

    cudaFuncSetAttribute(k_moe, cudaFuncAttributeMaxDynamicSharedMemorySize, SMEM_TOTAL);

    k_hist<<<HB, 256>>>((const int4*)rm);

    cudaLaunchAttribute pdl[1];
    pdl[0].id = cudaLaunchAttributeProgrammaticStreamSerialization;
    pdl[0].val.programmaticStreamSerializationAllowed = 1;

    cudaLaunchConfig_t cfg2 = {};
    cfg2.gridDim = dim3(HB + WCB);
    cfg2.blockDim = dim3(256);
    cfg2.attrs = pdl;
    cfg2.numAttrs = 1;
    cudaLaunchKernelEx(&cfg2, k_pre2, (const int4*)rm, W1, W2, W3, W4, W5, W6);

    cudaLaunchConfig_t cfg3 = {};
    cfg3.gridDim = dim3(TILES_PER_EXP, NEXP);
    cfg3.blockDim = dim3(NTHR);
    cfg3.dynamicSmemBytes = SMEM_TOTAL;
    cfg3.attrs = pdl;
    cfg3.numAttrs = 1;
    cudaLaunchKernelEx(&cfg3, k_moe, X, b1, b2, b3, b4, b5, b6, out);
}

// round 17
// speedup vs baseline: 1.1157x; 1.0403x over previous
#include <cuda_runtime.h>
#include <cuda_fp16.h>
#include <cstdint>

#define NB    65536
#define DIM   256
#define HID   64
#define ACT   18
#define NEXP  8
#define ROWS  256
#define NTHR  256
#define HPAD  72        // halves per row stride (144B) -> conflict-free ldmatrix
#define TILES_PER_EXP 64
#define CAP   (TILES_PER_EXP * ROWS)   // 16384 rows/expert bucket

// smem: W double buffer + bias
#define SWSZ   18432
#define SBIAS  (2 * SWSZ)
#define SMEM_TOTAL (SBIAS + 1408)

// ---------------- scratch ----------------
#define HB 64
__device__ int g_cnt[NEXP];
__device__ int g_perm[NEXP * CAP];
// per expert 9 slots (W1 c0..c3, W2..W5, W6) of 8192 halves:
// hi plane [0,4096), lo plane [4096,8192); layout [n][64 k]
__device__ __align__(16) __half g_w[NEXP * 9 * 8192];

#define WCB (NEXP * 9)

// ---------------- launch 1: zero bucket counters ----------------
__global__ void k_zero() {
    if (threadIdx.x < NEXP) g_cnt[threadIdx.x] = 0;
}

// ---------------- launch 2 (PDL): scatter (0..63, waits) || wconv (64..135, no wait) ----------------
__global__ void k_scatter(const int4* __restrict__ rm,
                          const float* __restrict__ W1, const float* __restrict__ W2,
                          const float* __restrict__ W3, const float* __restrict__ W4,
                          const float* __restrict__ W5, const float* __restrict__ W6) {
    __shared__ float sm[64 * 65];
    int b = blockIdx.x, t = threadIdx.x;
    if (b < HB) {
#if __CUDA_ARCH__ >= 900
        cudaGridDependencySynchronize();   // wait for k_zero
#endif
        int* s_cnt  = (int*)sm;
        int* s_base = (int*)sm + NEXP;
        if (t < NEXP) s_cnt[t] = 0;
        __syncthreads();
        int4 v = rm[b * 256 + t];
        int vv[4] = { v.x, v.y, v.z, v.w };
        int loc[4];
        unsigned lt = (1u << (t & 31)) - 1u;
        #pragma unroll
        for (int r = 0; r < 4; r++) {
            unsigned m = __match_any_sync(0xffffffffu, vv[r]);
            int leader = __ffs(m) - 1;
            int base = 0;
            if ((t & 31) == leader) base = atomicAdd(&s_cnt[vv[r]], __popc(m));
            base = __shfl_sync(0xffffffffu, base, leader);
            loc[r] = base + __popc(m & lt);
        }
        __syncthreads();
        if (t < NEXP) s_base[t] = atomicAdd(&g_cnt[t], s_cnt[t]);
        __syncthreads();
        int i4 = (b * 256 + t) * 4;
        #pragma unroll
        for (int r = 0; r < 4; r++)
            g_perm[vv[r] * CAP + s_base[vv[r]] + loc[r]] = i4 + r;
        return;
    }
    // ---- weight tile conversion (independent; runs immediately) ----
    int s = (b - HB) % 9, e = (b - HB) / 9;
    int base = (e * 9 + s) * 8192;
    if (s < 8) {
        const float* src;
        if (s < 4)       src = W1 + (size_t)e * 16384 + s * 4096;
        else if (s == 4) src = W2 + (size_t)e * 4096;
        else if (s == 5) src = W3 + (size_t)e * 4096;
        else if (s == 6) src = W4 + (size_t)e * 4096;
        else             src = W5 + (size_t)e * 4096;
        #pragma unroll
        for (int j = 0; j < 4; j++) {
            int f = t + j * 256;
            int row = f >> 4, c4 = (f & 15) * 4;
            float4 v = *(const float4*)(src + row * 64 + c4);
            float* d = sm + row * 65 + c4;
            d[0] = v.x; d[1] = v.y; d[2] = v.z; d[3] = v.w;
        }
        __syncthreads();
        int n = t >> 2, kb = (t & 3) * 16;
        __align__(16) __half hb[16], lb[16];
        #pragma unroll
        for (int kk = 0; kk < 16; kk++) {
            float w = sm[(kb + kk) * 65 + n];
            __half h = __float2half_rn(w);
            hb[kk] = h;
            lb[kk] = __float2half_rn(w - __half2float(h));
        }
        uint4* dh = (uint4*)&g_w[base + n * 64 + kb];
        dh[0] = *(uint4*)hb;  dh[1] = *(uint4*)(hb + 8);
        uint4* dl = (uint4*)&g_w[base + 4096 + n * 64 + kb];
        dl[0] = *(uint4*)lb;  dl[1] = *(uint4*)(lb + 8);
    } else {
        const float* src6 = W6 + (size_t)e * 64 * ACT;
        for (int i = t; i < 64 * ACT; i += 256)
            sm[(i / ACT) * 65 + (i % ACT)] = src6[i];
        __syncthreads();
        int n = t >> 3, kb = (t & 7) * 8;
        __align__(16) __half hb[8], lb[8];
        #pragma unroll
        for (int kk = 0; kk < 8; kk++) {
            float w = (n < ACT) ? sm[(kb + kk) * 65 + n] : 0.f;
            __half h = __float2half_rn(w);
            hb[kk] = h;
            lb[kk] = __float2half_rn(w - __half2float(h));
        }
        *(uint4*)&g_w[base + n * 64 + kb] = *(uint4*)hb;
        *(uint4*)&g_w[base + 4096 + n * 64 + kb] = *(uint4*)lb;
    }
}

// ---------------- helpers ----------------
__device__ __forceinline__ uint32_t smem_u32(const void* p) {
    uint32_t a;
    asm("{ .reg .u64 t; cvta.to.shared.u64 t, %1; cvt.u32.u64 %0, t; }" : "=r"(a) : "l"(p));
    return a;
}
__device__ __forceinline__ uint32_t pk2(float a, float b) {
    uint32_t r;
    asm("cvt.rn.f16x2.f32 %0, %1, %2;" : "=r"(r) : "f"(b), "f"(a));
    return r;
}
#define CP16(dst, src) \
    asm volatile("cp.async.ca.shared.global [%0], [%1], 16;" :: "r"(dst), "l"(src))
#define CP_COMMIT() asm volatile("cp.async.commit_group;" ::: "memory")
#define CP_WAIT0()  asm volatile("cp.async.wait_group 0;" ::: "memory")

#define LDSM4(d, addr) \
    asm volatile("ldmatrix.sync.aligned.m8n8.x4.shared.b16 {%0,%1,%2,%3}, [%4];" \
        : "=r"((d)[0]), "=r"((d)[1]), "=r"((d)[2]), "=r"((d)[3]) : "r"(addr))

// non-volatile: ptxas may interleave/software-pipeline the MMA stream
#define MMA(c, a, b0, b1) \
    asm("mma.sync.aligned.m16n8k16.row.col.f32.f16.f16.f32 " \
        "{%0,%1,%2,%3},{%4,%5,%6,%7},{%8,%9},{%0,%1,%2,%3};" \
        : "+f"((c)[0]), "+f"((c)[1]), "+f"((c)[2]), "+f"((c)[3]) \
        : "r"((a)[0]), "r"((a)[1]), "r"((a)[2]), "r"((a)[3]), "r"(b0), "r"(b1))

__device__ __forceinline__ void stageW(uint32_t swb, const __half* gw,
                                       int tid, int nW) {
    const char* src = (const char*)gw;
    int total = nW * 8;
    #pragma unroll 2
    for (int i = tid; i < total; i += NTHR) {
        int n = i >> 3, j = i & 7;
        uint32_t d = n * (HPAD * 2) + j * 16;
        int s = (n * 64 + j * 8) * 2;
        CP16(swb + d, src + s);
        CP16(swb + 9216 + d, src + 8192 + s);
    }
}

// 8 MMAs interleaved over 4 independent accumulator chains
#define MMA8I(aA, aB, fA, fB, bh, bl) do {               \
    MMA((aA)[0], fA, (bh)[0], (bh)[1]);                  \
    MMA((aA)[1], fA, (bh)[2], (bh)[3]);                  \
    MMA((aB)[0], fB, (bh)[0], (bh)[1]);                  \
    MMA((aB)[1], fB, (bh)[2], (bh)[3]);                  \
    MMA((aA)[0], fA, (bl)[0], (bl)[1]);                  \
    MMA((aA)[1], fA, (bl)[2], (bl)[3]);                  \
    MMA((aB)[0], fB, (bl)[0], (bl)[1]);                  \
    MMA((aB)[1], fB, (bl)[2], (bl)[3]);                  \
} while (0)

// ---------------- fused MoE (8 warps x 32 rows, fp16 2-term) ----------------
__global__ void __launch_bounds__(NTHR, 2) k_moe(
    const float* __restrict__ X,
    const float* __restrict__ b1, const float* __restrict__ b2,
    const float* __restrict__ b3, const float* __restrict__ b4,
    const float* __restrict__ b5, const float* __restrict__ b6,
    float* __restrict__ out)
{
    extern __shared__ char smem[];
    const int tid = threadIdx.x, wid = tid >> 5, lane = tid & 31;
    const int e = blockIdx.y, tile = blockIdx.x;

    const uint32_t sb = smem_u32(smem);
    const uint32_t wbuf[2] = { sb, sb + SWSZ };
    float* sB = (float*)(smem + SBIAS);

    // bias preload (pure inputs, safe before the PDL dependency sync)
    if (tid < 64) {
        sB[tid]       = b1[e * HID + tid];
        sB[64 + tid]  = b2[e * HID + tid];
        sB[128 + tid] = b3[e * HID + tid];
        sB[192 + tid] = b4[e * HID + tid];
        sB[256 + tid] = b5[e * HID + tid];
    }
    if (tid < 32) sB[320 + tid] = (tid < ACT) ? b6[e * ACT + tid] : 0.f;

#if __CUDA_ARCH__ >= 900
    cudaGridDependencySynchronize();   // wait for k_scatter grid (g_cnt, g_perm, g_w)
#endif

    const int off = e * CAP;
    const int cnt = min(g_cnt[e], CAP);
    if (tile * ROWS >= cnt) return;
    const int nrows = min(ROWS, cnt - tile * ROWS);

    const __half* gwE = g_w + (size_t)e * 9 * 8192;

    stageW(wbuf[0], gwE, tid, 64);
    CP_COMMIT();

    const uint32_t bRowL = (uint32_t)((lane & 7) + ((lane >> 4) & 1) * 8);
    const uint32_t bKof  = ((lane >> 3) & 1) * 8;

    const int erow = wid * 32 + (lane >> 2);
    int pr[4];
    const float* xr[4];
    #pragma unroll
    for (int q = 0; q < 4; q++) {
        int rr = erow + q * 8;
        pr[q] = (rr < nrows) ? g_perm[off + tile * ROWS + rr] : -1;
        xr[q] = X + (size_t)((pr[q] >= 0) ? pr[q] : g_perm[off]) * DIM;
    }
    const int cofL = (lane & 3) * 2;
    const int cofH = 8 + cofL;

    float accA[8][4], accB[8][4];
    #pragma unroll
    for (int i = 0; i < 8; i++)
        #pragma unroll
        for (int j = 0; j < 4; j++) { accA[i][j] = 0.f; accB[i][j] = 0.f; }

    float2 cur[8];
    #pragma unroll
    for (int q = 0; q < 2; q++) {
        cur[4 * q + 0] = *(const float2*)(xr[2 * q + 0] + cofL);
        cur[4 * q + 1] = *(const float2*)(xr[2 * q + 1] + cofL);
        cur[4 * q + 2] = *(const float2*)(xr[2 * q + 0] + cofH);
        cur[4 * q + 3] = *(const float2*)(xr[2 * q + 1] + cofH);
    }

    // ============ layer 1: 4 chunks of K=64 ============
    for (int c = 0; c < 4; c++) {
        CP_WAIT0();
        __syncthreads();
        stageW(wbuf[(c + 1) & 1], gwE + (c + 1) * 8192, tid, 64);
        CP_COMMIT();
        const uint32_t wb_ = wbuf[c & 1];
        #pragma unroll
        for (int ks = 0; ks < 4; ks++) {
            uint32_t fA[4], fB[4];
            #pragma unroll
            for (int q = 0; q < 4; q++) {
                fA[q] = pk2(cur[q].x, cur[q].y);
                fB[q] = pk2(cur[4 + q].x, cur[4 + q].y);
            }
            if (!(c == 3 && ks == 3)) {
                int kb = c * 64 + (ks + 1) * 16;
                if (ks == 3) kb = (c + 1) * 64;
                #pragma unroll
                for (int q = 0; q < 2; q++) {
                    cur[4 * q + 0] = *(const float2*)(xr[2 * q + 0] + kb + cofL);
                    cur[4 * q + 1] = *(const float2*)(xr[2 * q + 1] + kb + cofL);
                    cur[4 * q + 2] = *(const float2*)(xr[2 * q + 0] + kb + cofH);
                    cur[4 * q + 3] = *(const float2*)(xr[2 * q + 1] + kb + cofH);
                }
            }
            uint32_t k0 = ks * 16;
            #pragma unroll
            for (int p = 0; p < 4; p++) {
                uint32_t boff = ((p * 16 + bRowL) * HPAD + k0 + bKof) * 2;
                uint32_t bh[4], bl[4];
                LDSM4(bh, wb_ + boff);
                LDSM4(bl, wb_ + 9216 + boff);
                MMA8I((accA + 2 * p), (accB + 2 * p), fA, fB, bh, bl);
            }
        }
    }

    // ============ layers 2..5 (stages 4..7) ============
    for (int s = 4; s < 8; s++) {
        CP_WAIT0();
        __syncthreads();
        stageW(wbuf[(s + 1) & 1], gwE + (s + 1) * 8192, tid, (s == 7) ? 32 : 64);
        CP_COMMIT();
        const float* bb = sB + (s - 4) * 64;
        uint32_t fA[4][4], fB[4][4];
        #pragma unroll
        for (int kt = 0; kt < 4; kt++) {
            #pragma unroll
            for (int h = 0; h < 2; h++) {
                int nt = 2 * kt + h;
                float b0v = bb[nt * 8 + cofL], b1v = bb[nt * 8 + cofL + 1];
                float v0 = fmaxf(accA[nt][0] + b0v, 0.f);
                float v1 = fmaxf(accA[nt][1] + b1v, 0.f);
                float v2 = fmaxf(accA[nt][2] + b0v, 0.f);
                float v3 = fmaxf(accA[nt][3] + b1v, 0.f);
                fA[kt][2 * h]     = pk2(v0, v1);
                fA[kt][2 * h + 1] = pk2(v2, v3);
                float w0 = fmaxf(accB[nt][0] + b0v, 0.f);
                float w1 = fmaxf(accB[nt][1] + b1v, 0.f);
                float w2 = fmaxf(accB[nt][2] + b0v, 0.f);
                float w3 = fmaxf(accB[nt][3] + b1v, 0.f);
                fB[kt][2 * h]     = pk2(w0, w1);
                fB[kt][2 * h + 1] = pk2(w2, w3);
            }
        }
        #pragma unroll
        for (int i = 0; i < 8; i++)
            #pragma unroll
            for (int j = 0; j < 4; j++) { accA[i][j] = 0.f; accB[i][j] = 0.f; }
        #pragma unroll
        for (int ks = 0; ks < 4; ks++) {
            uint32_t k0 = ks * 16;
            #pragma unroll
            for (int p = 0; p < 4; p++) {
                uint32_t boff = ((p * 16 + bRowL) * HPAD + k0 + bKof) * 2;
                uint32_t bh[4], bl[4];
                LDSM4(bh, wbuf[s & 1] + boff);
                LDSM4(bl, wbuf[s & 1] + 9216 + boff);
                MMA8I((accA + 2 * p), (accB + 2 * p), fA[ks], fB[ks], bh, bl);
            }
        }
    }

    // ============ layer 6 (stage 8) ============
    CP_WAIT0();
    __syncthreads();
    {
        const float* bb = sB + 256;
        uint32_t fA[4][4], fB[4][4];
        #pragma unroll
        for (int kt = 0; kt < 4; kt++) {
            #pragma unroll
            for (int h = 0; h < 2; h++) {
                int nt = 2 * kt + h;
                float b0v = bb[nt * 8 + cofL], b1v = bb[nt * 8 + cofL + 1];
                float v0 = fmaxf(accA[nt][0] + b0v, 0.f);
                float v1 = fmaxf(accA[nt][1] + b1v, 0.f);
                float v2 = fmaxf(accA[nt][2] + b0v, 0.f);
                float v3 = fmaxf(accA[nt][3] + b1v, 0.f);
                fA[kt][2 * h]     = pk2(v0, v1);
                fA[kt][2 * h + 1] = pk2(v2, v3);
                float w0 = fmaxf(accB[nt][0] + b0v, 0.f);
                float w1 = fmaxf(accB[nt][1] + b1v, 0.f);
                float w2 = fmaxf(accB[nt][2] + b0v, 0.f);
                float w3 = fmaxf(accB[nt][3] + b1v, 0.f);
                fB[kt][2 * h]     = pk2(w0, w1);
                fB[kt][2 * h + 1] = pk2(w2, w3);
            }
        }
        float acc6A[4][4], acc6B[4][4];
        #pragma unroll
        for (int i = 0; i < 4; i++)
            #pragma unroll
            for (int j = 0; j < 4; j++) { acc6A[i][j] = 0.f; acc6B[i][j] = 0.f; }

        const uint32_t wb_ = wbuf[0];
        #pragma unroll
        for (int ks = 0; ks < 4; ks++) {
            uint32_t k0 = ks * 16;
            #pragma unroll
            for (int p = 0; p < 2; p++) {
                uint32_t boff = ((p * 16 + bRowL) * HPAD + k0 + bKof) * 2;
                uint32_t bh[4], bl[4];
                LDSM4(bh, wb_ + boff);
                LDSM4(bl, wb_ + 9216 + boff);
                MMA8I((acc6A + 2 * p), (acc6B + 2 * p), fA[ks], fB[ks], bh, bl);
            }
        }

        const float* b6b = sB + 320;
        #pragma unroll
        for (int nt = 0; nt < 3; nt++) {
            int c0 = nt * 8 + cofL;
            if (c0 + 1 < ACT) {
                float b0v = b6b[c0], b1v = b6b[c0 + 1];
                if (pr[0] >= 0) {
                    out[(size_t)pr[0] * ACT + c0]     = acc6A[nt][0] + b0v;
                    out[(size_t)pr[0] * ACT + c0 + 1] = acc6A[nt][1] + b1v;
                }
                if (pr[1] >= 0) {
                    out[(size_t)pr[1] * ACT + c0]     = acc6A[nt][2] + b0v;
                    out[(size_t)pr[1] * ACT + c0 + 1] = acc6A[nt][3] + b1v;
                }
                if (pr[2] >= 0) {
                    out[(size_t)pr[2] * ACT + c0]     = acc6B[nt][0] + b0v;
                    out[(size_t)pr[2] * ACT + c0 + 1] = acc6B[nt][1] + b1v;
                }
                if (pr[3] >= 0) {
                    out[(size_t)pr[3] * ACT + c0]     = acc6B[nt][2] + b0v;
                    out[(size_t)pr[3] * ACT + c0 + 1] = acc6B[nt][3] + b1v;
                }
            }
        }
    }
}

extern "C" void kernel_launch(void* const* d_in, const int* in_sizes, int n_in,
                              void* d_out, int out_size) {
    const float* X  = (const float*)d_in[0];
    const int*   rm = (const int*)d_in[1];
    const float* W1 = (const float*)d_in[2];  const float* b1 = (const float*)d_in[3];
    const float* W2 = (const float*)d_in[4];  const float* b2 = (const float*)d_in[5];
    const float* W3 = (const float*)d_in[6];  const float* b3 = (const float*)d_in[7];
    const float* W4 = (const float*)d_in[8];  const float* b4 = (const float*)d_in[9];
    const float* W5 = (const float*)d_in[10]; const float* b5 = (const float*)d_in[11];
    const float* W6 = (const float*)d_in[12]; const float* b6 = (const float*)d_in[13];
    float* out = (float*)d_out;

    cudaFuncSetAttribute(k_moe, cudaFuncAttributeMaxDynamicSharedMemorySize, SMEM_TOTAL);

    k_zero<<<1, 32>>>();

    cudaLaunchAttribute pdl[1];
    pdl[0].id = cudaLaunchAttributeProgrammaticStreamSerialization;
    pdl[0].val.programmaticStreamSerializationAllowed = 1;

    cudaLaunchConfig_t cfg2 = {};
    cfg2.gridDim = dim3(HB + WCB);
    cfg2.blockDim = dim3(256);
    cfg2.attrs = pdl;
    cfg2.numAttrs = 1;
    cudaLaunchKernelEx(&cfg2, k_scatter, (const int4*)rm, W1, W2, W3, W4, W5, W6);

    cudaLaunchConfig_t cfg3 = {};
    cfg3.gridDim = dim3(TILES_PER_EXP, NEXP);
    cfg3.blockDim = dim3(NTHR);
    cfg3.dynamicSmemBytes = SMEM_TOTAL;
    cfg3.attrs = pdl;
    cfg3.numAttrs = 1;
    cudaLaunchKernelEx(&cfg3, k_moe, X, b1, b2, b3, b4, b5, b6, out);
}